// round 13
// baseline (speedup 1.0000x reference)
#include <cuda_runtime.h>

// ---------------- problem constants ----------------
#define D_      128
#define TWO_D   256
#define NINIT   100000
#define LVLS    64
#define MM      4096
#define NRULES  256
#define NTOT    (NINIT + LVLS * MM)   // 362144

#define EVAL_BLOCKS 1024
#define PBLK  128    // persistent blocks (1/SM, all resident; 2 rules each)
#define CHUNK 16     // nodes per gather chunk (4 g-slots x NN=4)
#define WIN   64     // node-index window staged per rule

// dynamic smem for k_levels:
//   w_s  float2[256][64]          131072 B  (full rule weight matrix)
//   raw  float[2][CHUNK][256]      32768 B  (gathered parents, dbl buf)
//   pe2  float2[CHUNK][256]        32768 B  (duplicated (v,v) pairs)
//   s_m[WIN] + s_par[WIN][2] + mbar[3]
#define WS_B   131072
#define RAW_B  32768
#define PE2_B  32768
#define IDX_B  (WIN * 4 + WIN * 8)
#define SMEM_LVL (WS_B + RAW_B + PE2_B + IDX_B + 64)   // ~197 KB

// ---------------- device scratch (static: no allocs allowed) ----------------
__device__ float    g_store[(size_t)NTOT * D_];     // ~185 MB embedding store
__device__ int      g_order[LVLS * MM];             // node ids grouped by rule/level
__device__ int      g_off[LVLS * (NRULES + 1)];     // per-level rule offsets
__device__ double   g_part[EVAL_BLOCKS * 8];        // eval partial sums
__device__ unsigned g_bar;                          // grid barrier (0 at rest)

// ---------------- helpers ----------------
union F2U { float2 f; unsigned long long u; };
union F4U { float4 f; unsigned long long u[2]; };

__device__ __forceinline__ void ffma2(unsigned long long& d,
                                      unsigned long long a,
                                      unsigned long long b) {
    asm("fma.rn.f32x2 %0, %1, %2, %0;" : "+l"(d) : "l"(a), "l"(b));
}
__device__ __forceinline__ void mbar_init(unsigned mbar, unsigned count) {
    asm volatile("mbarrier.init.shared.b64 [%0], %1;" :: "r"(mbar), "r"(count) : "memory");
}
__device__ __forceinline__ void mbar_expect_tx(unsigned mbar, unsigned bytes) {
    asm volatile("mbarrier.arrive.expect_tx.shared.b64 _, [%0], %1;"
                 :: "r"(mbar), "r"(bytes) : "memory");
}
__device__ __forceinline__ void bulk_g2s(unsigned dst, const void* src,
                                         unsigned bytes, unsigned mbar) {
    asm volatile("cp.async.bulk.shared::cta.global.mbarrier::complete_tx::bytes "
                 "[%0], [%1], %2, [%3];"
                 :: "r"(dst), "l"(src), "r"(bytes), "r"(mbar) : "memory");
}
__device__ __forceinline__ void mbar_wait(unsigned mbar, unsigned phase) {
    asm volatile(
        "{\n\t"
        ".reg .pred p;\n\t"
        "WL%=:\n\t"
        "mbarrier.try_wait.parity.acquire.cta.shared::cta.b64 p, [%0], %1, 0x989680;\n\t"
        "@!p bra WL%=;\n\t"
        "}"
        :: "r"(mbar), "r"(phase) : "memory");
}
__device__ __forceinline__ float softplusf(float x) {
    return fmaxf(x, 0.0f) + log1pf(expf(-fabsf(x)));
}

// ---------------- 1. init embeddings ----------------
__global__ void k_init(const float* __restrict__ thax_table,
                       const float* __restrict__ sine_table,
                       const int* __restrict__ init_thax,
                       const int* __restrict__ init_sine) {
    int idx = blockIdx.x * blockDim.x + threadIdx.x;
    if (idx >= NINIT * 32) return;
    int row = idx >> 5, q = idx & 31;
    int t = init_thax[row], s = init_sine[row];
    const float4 a = *(const float4*)(thax_table + (size_t)t * D_ + q * 4);
    const float4 b = *(const float4*)(sine_table + (size_t)s * D_ + q * 4);
    float4 o; o.x = a.x + b.x; o.y = a.y + b.y; o.z = a.z + b.z; o.w = a.w + b.w;
    *(float4*)(g_store + (size_t)row * D_ + q * 4) = o;
}

// ---------------- 2. bucket nodes by rule, per level ----------------
__global__ void k_group(const int* __restrict__ rules) {
    int l = blockIdx.x;
    int tid = threadIdx.x;                    // 256 threads
    __shared__ int cnt[NRULES];
    __shared__ int base[NRULES];
    cnt[tid] = 0;
    __syncthreads();
    for (int m = tid; m < MM; m += 256)
        atomicAdd(&cnt[rules[l * MM + m]], 1);
    __syncthreads();
    if (tid == 0) {
        int acc = 0;
        for (int r = 0; r < NRULES; r++) { base[r] = acc; acc += cnt[r]; }
    }
    __syncthreads();
    g_off[l * (NRULES + 1) + tid] = base[tid];
    if (tid == 0) g_off[l * (NRULES + 1) + NRULES] = MM;
    cnt[tid] = 0;
    __syncthreads();
    for (int m = tid; m < MM; m += 256) {
        int r = rules[l * MM + m];
        int pos = base[r] + atomicAdd(&cnt[r], 1);
        g_order[l * MM + pos] = m;
    }
}

// ---------------- 3. persistent level kernel -------------------------------
// 128 blocks x 256 threads, all resident (1/SM). Block b owns rules 2b,2b+1.
// All 64 levels inside one kernel, separated by a software grid barrier, so
// rule_W stays L2-resident (reuse distance ~40MB < 126MB) instead of being
// re-streamed from DRAM on every launch. Weights: one 128KB bulk copy per
// rule per level. Gathers: bulk-DMA per 512B parent row, double-buffered.
// Compute: FFMA2 pairs from SMEM (duplicated pe), 64 col-pairs x 4 slots,
// NN=4 nodes/thread.
__global__ void __launch_bounds__(256) k_levels(
    const float* __restrict__ rule_W, const float* __restrict__ rule_b,
    const int* __restrict__ parents) {

    extern __shared__ __align__(16) char sm[];
    float2* w_s = (float2*)sm;                                   // [256][64]
    float*  raw = (float*)(sm + WS_B);                           // [2][16][256]
    float2* pe2 = (float2*)(sm + WS_B + RAW_B);                  // [16][256]
    int*    s_m = (int*)(sm + WS_B + RAW_B + PE2_B);             // [WIN]
    int*    s_par = s_m + WIN;                                   // [WIN][2]
    unsigned long long* mb = (unsigned long long*)(s_par + 2 * WIN);

    unsigned mb_w  = (unsigned)__cvta_generic_to_shared(&mb[0]);
    unsigned mb_g0 = (unsigned)__cvta_generic_to_shared(&mb[1]);
    unsigned mb_g1 = (unsigned)__cvta_generic_to_shared(&mb[2]);
    unsigned raw_sh = (unsigned)__cvta_generic_to_shared(raw);

    int tid = threadIdx.x;
    int j   = tid & 63;            // col-pair 0..63 (cols 2j,2j+1)
    int g   = tid >> 6;            // node slot 0..3

    if (tid == 0) { mbar_init(mb_w, 1); mbar_init(mb_g0, 1); mbar_init(mb_g1, 1); }
    __syncthreads();

    unsigned wph = 0, gph0 = 0, gph1 = 0;

    for (int lvl = 0; lvl < LVLS; lvl++) {
        int out0 = NINIT + lvl * MM;

        for (int rr = 0; rr < 2; rr++) {
            int r = blockIdx.x * 2 + rr;
            int off0 = g_off[lvl * (NRULES + 1) + r];
            int c = g_off[lvl * (NRULES + 1) + r + 1] - off0;
            if (c == 0) continue;

            // weights: one 128KB bulk copy (L2 hit from level 1 on)
            if (tid == 0) {
                mbar_expect_tx(mb_w, WS_B);
                bulk_g2s((unsigned)__cvta_generic_to_shared(w_s),
                         rule_W + (size_t)r * TWO_D * D_, WS_B, mb_w);
            }
            F2U bpk; bpk.f = *(const float2*)(rule_b + (size_t)r * D_ + 2 * j);
            bool wready = false;

            for (int w0 = 0; w0 < c; w0 += WIN) {
                int wlen = min(WIN, c - w0);
                if (tid < 2 * wlen) {
                    int n = tid >> 1, pw = tid & 1;
                    int m = g_order[lvl * MM + off0 + w0 + n];
                    int p = parents[((size_t)lvl * MM + m) * 2 + pw];
                    if (pw == 0) s_m[n] = m;
                    s_par[n * 2 + pw] = p;
                }
                __syncthreads();

                int nc = (wlen + CHUNK - 1) / CHUNK;

                auto gather = [&](int buf, int t) {
                    int nch = min(CHUNK, wlen - t * CHUNK);
                    unsigned mbar = buf ? mb_g1 : mb_g0;
                    mbar_expect_tx(mbar, (unsigned)(nch * 2 * 512));
                    for (int i = 0; i < 2 * nch; i++) {
                        int n = i >> 1, par = i & 1;
                        int p = s_par[(t * CHUNK + n) * 2 + par];
                        bulk_g2s(raw_sh + (unsigned)(((buf * CHUNK + n) * TWO_D + par * D_) * 4),
                                 g_store + (size_t)p * D_, 512, mbar);
                    }
                };

                if (tid == 0) gather(0, 0);

                for (int t = 0; t < nc; t++) {
                    int buf = t & 1;
                    if (t + 1 < nc && tid == 0) gather(buf ^ 1, t + 1);

                    if (buf == 0) { mbar_wait(mb_g0, gph0); gph0 ^= 1u; }
                    else          { mbar_wait(mb_g1, gph1); gph1 ^= 1u; }
                    if (!wready) { mbar_wait(mb_w, wph); wph ^= 1u; wready = true; }

                    // duplication pass: raw (v0..v3) -> pe2 ((v,v) pairs)
                    {
                        const float* rb = raw + (size_t)buf * CHUNK * TWO_D;
#pragma unroll
                        for (int it = 0; it < 4; it++) {
                            int i = it * 256 + tid;          // [16 n][64 k4]
                            int n = i >> 6, k4 = i & 63;
                            float4 v = *(const float4*)(rb + n * TWO_D + k4 * 4);
                            *(float4*)&pe2[n * TWO_D + k4 * 4 + 0] =
                                make_float4(v.x, v.x, v.y, v.y);
                            *(float4*)&pe2[n * TWO_D + k4 * 4 + 2] =
                                make_float4(v.z, v.z, v.w, v.w);
                        }
                    }
                    __syncthreads();

                    unsigned long long a0 = bpk.u, a1 = bpk.u, a2 = bpk.u, a3 = bpk.u;
#pragma unroll 8
                    for (int kp = 0; kp < TWO_D / 2; kp++) {
                        F2U w0; w0.f = w_s[(2 * kp) * 64 + j];
                        F2U w1; w1.f = w_s[(2 * kp + 1) * 64 + j];
                        F4U p0; p0.f = *(const float4*)&pe2[(g * 4 + 0) * TWO_D + 2 * kp];
                        F4U p1; p1.f = *(const float4*)&pe2[(g * 4 + 1) * TWO_D + 2 * kp];
                        F4U p2; p2.f = *(const float4*)&pe2[(g * 4 + 2) * TWO_D + 2 * kp];
                        F4U p3; p3.f = *(const float4*)&pe2[(g * 4 + 3) * TWO_D + 2 * kp];
                        ffma2(a0, w0.u, p0.u[0]); ffma2(a0, w1.u, p0.u[1]);
                        ffma2(a1, w0.u, p1.u[0]); ffma2(a1, w1.u, p1.u[1]);
                        ffma2(a2, w0.u, p2.u[0]); ffma2(a2, w1.u, p2.u[1]);
                        ffma2(a3, w0.u, p3.u[0]); ffma2(a3, w1.u, p3.u[1]);
                    }

                    int nb = t * CHUNK + g * 4;
                    unsigned long long accs[4] = {a0, a1, a2, a3};
#pragma unroll
                    for (int nn = 0; nn < 4; nn++) {
                        if (nb + nn < wlen) {
                            F2U o; o.u = accs[nn];
                            o.f.x = fmaxf(o.f.x, 0.0f);
                            o.f.y = fmaxf(o.f.y, 0.0f);
                            *(float2*)(g_store + (size_t)(out0 + s_m[nb + nn]) * D_ + 2 * j) = o.f;
                        }
                    }
                    __syncthreads();   // raw/pe2/idx safe to reuse
                }
            }
        }

        // ---- software grid barrier between levels ----
        __threadfence();              // publish this thread's stores
        __syncthreads();              // all block threads fenced
        if (lvl < LVLS - 1) {
            if (tid == 0) {
                atomicAdd(&g_bar, 1u);
                unsigned target = (unsigned)(lvl + 1) * PBLK;
                while (atomicAdd(&g_bar, 0u) < target) __nanosleep(64);
            }
            __syncthreads();
            __threadfence();
        } else {
            if (tid == 0) {
                unsigned old = atomicAdd(&g_bar, 1u);
                if (old == (unsigned)LVLS * PBLK - 1u)
                    atomicExch(&g_bar, 0u);   // last arrival resets for next replay
            }
        }
    }
}

// ---------------- 4. eval: logits + weighted BCE, deterministic reduce ------
__global__ void k_eval(const float* __restrict__ eval_w,
                       const float* __restrict__ eval_b,
                       const float* __restrict__ pos_vals,
                       const float* __restrict__ neg_vals) {
    int warp = threadIdx.x >> 5, lane = threadIdx.x & 31;
    int nwarps = gridDim.x * (blockDim.x >> 5);
    int gw = blockIdx.x * (blockDim.x >> 5) + warp;

    const float4 wv = *(const float4*)(eval_w + lane * 4);
    float eb = eval_b[0];

    double s1 = 0, s2 = 0, pok = 0, nok = 0, sp = 0, sn = 0;

    for (int node = gw; node < NTOT; node += nwarps) {
        float4 x = *(const float4*)(g_store + (size_t)node * D_ + lane * 4);
        float d = x.x * wv.x + x.y * wv.y + x.z * wv.z + x.w * wv.w;
#pragma unroll
        for (int o = 16; o > 0; o >>= 1) d += __shfl_xor_sync(0xFFFFFFFFu, d, o);
        if (lane == 0) {
            float logit = d + eb;
            float p = pos_vals[node], n = neg_vals[node];
            s1 += (double)(p * softplusf(-logit));
            s2 += (double)(n * softplusf(logit));
            if (logit >= 0.0f) pok += (double)p; else nok += (double)n;
            sp += (double)p; sn += (double)n;
        }
    }

    __shared__ double sd[8][6];
    if (lane == 0) {
        sd[warp][0] = s1; sd[warp][1] = s2; sd[warp][2] = pok;
        sd[warp][3] = nok; sd[warp][4] = sp; sd[warp][5] = sn;
    }
    __syncthreads();
    if (threadIdx.x == 0) {
        double v[6] = {0, 0, 0, 0, 0, 0};
        for (int w = 0; w < 8; w++)
            for (int c2 = 0; c2 < 6; c2++) v[c2] += sd[w][c2];
        for (int c2 = 0; c2 < 6; c2++) g_part[blockIdx.x * 8 + c2] = v[c2];
    }
}

__global__ void k_final(float* __restrict__ out) {
    __shared__ double sh[6][256];
    int tid = threadIdx.x;
    double v[6] = {0, 0, 0, 0, 0, 0};
    for (int b = tid; b < EVAL_BLOCKS; b += 256)
        for (int c2 = 0; c2 < 6; c2++) v[c2] += g_part[b * 8 + c2];
    for (int c2 = 0; c2 < 6; c2++) sh[c2][tid] = v[c2];
    __syncthreads();
    for (int s = 128; s > 0; s >>= 1) {
        if (tid < s)
            for (int c2 = 0; c2 < 6; c2++) sh[c2][tid] += sh[c2][tid + s];
        __syncthreads();
    }
    if (tid == 0) {
        double S1 = sh[0][0], S2 = sh[1][0], pok = sh[2][0];
        double nok = sh[3][0], sp = sh[4][0], sn = sh[5][0];
        double pw = sn / sp;
        out[0] = (float)(pw * S1 + S2);
        out[1] = (float)pok;
        out[2] = (float)nok;
    }
}

// ---------------- launch ----------------
extern "C" void kernel_launch(void* const* d_in, const int* in_sizes, int n_in,
                              void* d_out, int out_size) {
    const float* thax_table = (const float*)d_in[0];
    const float* sine_table = (const float*)d_in[1];
    const float* rule_W     = (const float*)d_in[2];
    const float* rule_b     = (const float*)d_in[3];
    const float* eval_w     = (const float*)d_in[4];
    const float* eval_b     = (const float*)d_in[5];
    const float* pos_vals   = (const float*)d_in[6];
    const float* neg_vals   = (const float*)d_in[7];
    const int*   init_thax  = (const int*)d_in[8];
    const int*   init_sine  = (const int*)d_in[9];
    const int*   parents    = (const int*)d_in[10];
    const int*   rules      = (const int*)d_in[11];

    (void)in_sizes; (void)n_in; (void)out_size;

    cudaFuncSetAttribute(k_levels, cudaFuncAttributeMaxDynamicSharedMemorySize,
                         SMEM_LVL);

    k_init<<<(NINIT * 32 + 255) / 256, 256>>>(thax_table, sine_table, init_thax, init_sine);
    k_group<<<LVLS, 256>>>(rules);
    k_levels<<<PBLK, 256, SMEM_LVL>>>(rule_W, rule_b, parents);
    k_eval<<<EVAL_BLOCKS, 256>>>(eval_w, eval_b, pos_vals, neg_vals);
    k_final<<<1, 256>>>((float*)d_out);
}

// round 15
// speedup vs baseline: 1.4180x; 1.4180x over previous
#include <cuda_runtime.h>

// ---------------- problem constants ----------------
#define D_      128
#define TWO_D   256
#define NINIT   100000
#define LVLS    64
#define MM      4096
#define NRULES  256
#define NTOT    (NINIT + LVLS * MM)   // 362144

#define EVAL_BLOCKS 1024
#define PBLK  256    // persistent blocks: 1 rule each, 2 resident per SM
#define CHUNK 16     // nodes per gather chunk (4 g-slots x NN=4)

// dynamic smem for k_levels:
//   w_s  float[128][128]   65536 B  (one K-half of the rule weight matrix)
//   raw  float[2][16][256] 32768 B  (gathered parents, dbl buf)
//   s_m  int[2][16], s_par int[2][16][2], mbar u64[3]
#define WS_B   65536
#define RAW_B  32768
#define IDX_B  (2*16*4 + 2*32*4)
#define SMEM_LVL (WS_B + RAW_B + IDX_B + 64)   // ~98.7 KB -> 2 blocks/SM

// ---------------- device scratch (static: no allocs allowed) ----------------
__device__ float    g_store[(size_t)NTOT * D_];     // ~185 MB embedding store
__device__ int      g_order[LVLS * MM];
__device__ int      g_off[LVLS * (NRULES + 1)];
__device__ double   g_part[EVAL_BLOCKS * 8];
__device__ unsigned g_bar;                          // grid barrier (0 at rest)

// ---------------- helpers ----------------
__device__ __forceinline__ void mbar_init(unsigned mbar, unsigned count) {
    asm volatile("mbarrier.init.shared.b64 [%0], %1;" :: "r"(mbar), "r"(count) : "memory");
}
__device__ __forceinline__ void mbar_expect_tx(unsigned mbar, unsigned bytes) {
    asm volatile("mbarrier.arrive.expect_tx.shared.b64 _, [%0], %1;"
                 :: "r"(mbar), "r"(bytes) : "memory");
}
__device__ __forceinline__ void bulk_g2s(unsigned dst, const void* src,
                                         unsigned bytes, unsigned mbar) {
    asm volatile("cp.async.bulk.shared::cta.global.mbarrier::complete_tx::bytes "
                 "[%0], [%1], %2, [%3];"
                 :: "r"(dst), "l"(src), "r"(bytes), "r"(mbar) : "memory");
}
__device__ __forceinline__ void mbar_wait(unsigned mbar, unsigned phase) {
    asm volatile(
        "{\n\t"
        ".reg .pred p;\n\t"
        "WL%=:\n\t"
        "mbarrier.try_wait.parity.acquire.cta.shared::cta.b64 p, [%0], %1, 0x989680;\n\t"
        "@!p bra WL%=;\n\t"
        "}"
        :: "r"(mbar), "r"(phase) : "memory");
}
__device__ __forceinline__ float softplusf(float x) {
    return fmaxf(x, 0.0f) + log1pf(expf(-fabsf(x)));
}

// ---------------- 1. init embeddings ----------------
__global__ void k_init(const float* __restrict__ thax_table,
                       const float* __restrict__ sine_table,
                       const int* __restrict__ init_thax,
                       const int* __restrict__ init_sine) {
    int idx = blockIdx.x * blockDim.x + threadIdx.x;
    if (idx >= NINIT * 32) return;
    int row = idx >> 5, q = idx & 31;
    int t = init_thax[row], s = init_sine[row];
    const float4 a = *(const float4*)(thax_table + (size_t)t * D_ + q * 4);
    const float4 b = *(const float4*)(sine_table + (size_t)s * D_ + q * 4);
    float4 o; o.x = a.x + b.x; o.y = a.y + b.y; o.z = a.z + b.z; o.w = a.w + b.w;
    *(float4*)(g_store + (size_t)row * D_ + q * 4) = o;
}

// ---------------- 2. bucket nodes by rule, per level ----------------
__global__ void k_group(const int* __restrict__ rules) {
    int l = blockIdx.x;
    int tid = threadIdx.x;                    // 256 threads
    __shared__ int cnt[NRULES];
    __shared__ int base[NRULES];
    cnt[tid] = 0;
    __syncthreads();
    for (int m = tid; m < MM; m += 256)
        atomicAdd(&cnt[rules[l * MM + m]], 1);
    __syncthreads();
    if (tid == 0) {
        int acc = 0;
        for (int r = 0; r < NRULES; r++) { base[r] = acc; acc += cnt[r]; }
    }
    __syncthreads();
    g_off[l * (NRULES + 1) + tid] = base[tid];
    if (tid == 0) g_off[l * (NRULES + 1) + NRULES] = MM;
    cnt[tid] = 0;
    __syncthreads();
    for (int m = tid; m < MM; m += 256) {
        int r = rules[l * MM + m];
        int pos = base[r] + atomicAdd(&cnt[r], 1);
        g_order[l * MM + pos] = m;
    }
}

// ---------------- 3. persistent level kernel -------------------------------
// 256 persistent blocks x 256 threads, 2 blocks/SM (all resident). Block b
// owns rule b for every level; levels separated by a software grid barrier.
// Per chunk of 16 nodes: gathers double-buffered via bulk-DMA; weights
// streamed as two contiguous 64KB K-half bulk copies. Co-resident block's
// compute hides this block's TMA waits.
__global__ void __launch_bounds__(256, 2) k_levels(
    const float* __restrict__ rule_W, const float* __restrict__ rule_b,
    const int* __restrict__ parents) {

    extern __shared__ __align__(16) char sm[];
    float* w_s = (float*)sm;                           // [128][128] one K-half
    float* raw = (float*)(sm + WS_B);                  // [2][16][256]
    int*   s_m   = (int*)(sm + WS_B + RAW_B);          // [2][16]
    int*   s_par = s_m + 32;                           // [2][16][2]
    unsigned long long* mb = (unsigned long long*)(s_par + 64);

    unsigned mb_w  = (unsigned)__cvta_generic_to_shared(&mb[0]);
    unsigned mb_g0 = (unsigned)__cvta_generic_to_shared(&mb[1]);
    unsigned mb_g1 = (unsigned)__cvta_generic_to_shared(&mb[2]);
    unsigned w_sh  = (unsigned)__cvta_generic_to_shared(w_s);
    unsigned raw_sh = (unsigned)__cvta_generic_to_shared(raw);

    int tid = threadIdx.x;
    int j   = tid & 63;            // col-pair 0..63 (cols 2j, 2j+1)
    int g   = tid >> 6;            // node group 0..3 (nodes g*4..g*4+3)
    int r   = blockIdx.x;          // this block's rule, all levels

    if (tid == 0) { mbar_init(mb_w, 1); mbar_init(mb_g0, 1); mbar_init(mb_g1, 1); }
    __syncthreads();

    unsigned wph = 0, gph0 = 0, gph1 = 0;
    const float* Wr = rule_W + (size_t)r * TWO_D * D_;
    const float2 bp = *(const float2*)(rule_b + (size_t)r * D_ + 2 * j);

    for (int lvl = 0; lvl < LVLS; lvl++) {
        int off0 = g_off[lvl * (NRULES + 1) + r];
        int c = g_off[lvl * (NRULES + 1) + r + 1] - off0;
        int out0 = NINIT + lvl * MM;

        if (c > 0) {
            int nc = (c + CHUNK - 1) / CHUNK;

            // stage idx for chunk 0 into parity buffer 0
            {
                int wl = min(CHUNK, c);
                if (tid < 2 * wl) {
                    int n = tid >> 1, pw = tid & 1;
                    int m = g_order[lvl * MM + off0 + n];
                    int p = parents[((size_t)lvl * MM + m) * 2 + pw];
                    if (pw == 0) s_m[n] = m;           // [0][n]
                    s_par[n * 2 + pw] = p;             // [0][n][pw]
                }
            }
            __syncthreads();
            if (tid == 0) {
                // gather chunk 0 (buf 0)
                int wl = min(CHUNK, c);
                mbar_expect_tx(mb_g0, (unsigned)(wl * 2 * 512));
                for (int i = 0; i < 2 * wl; i++) {
                    int n = i >> 1, par = i & 1;
                    int p = s_par[n * 2 + par];
                    bulk_g2s(raw_sh + (unsigned)((n * TWO_D + par * D_) * 4),
                             g_store + (size_t)p * D_, 512, mb_g0);
                }
                // weights K-half 0
                mbar_expect_tx(mb_w, WS_B);
                bulk_g2s(w_sh, Wr, WS_B, mb_w);
            }

            for (int t = 0; t < nc; t++) {
                int ib = t & 1;
                int wlen = min(CHUNK, c - t * CHUNK);

                // stage idx for chunk t+1 (opposite parity)
                if (t + 1 < nc) {
                    int wl2 = min(CHUNK, c - (t + 1) * CHUNK);
                    if (tid < 2 * wl2) {
                        int n = tid >> 1, pw = tid & 1;
                        int m = g_order[lvl * MM + off0 + (t + 1) * CHUNK + n];
                        int p = parents[((size_t)lvl * MM + m) * 2 + pw];
                        if (pw == 0) s_m[(ib ^ 1) * 16 + n] = m;
                        s_par[((ib ^ 1) * 16 + n) * 2 + pw] = p;
                    }
                }
                __syncthreads();
                if (tid == 0 && t + 1 < nc) {
                    int wl2 = min(CHUNK, c - (t + 1) * CHUNK);
                    unsigned mg = (ib ^ 1) ? mb_g1 : mb_g0;
                    mbar_expect_tx(mg, (unsigned)(wl2 * 2 * 512));
                    for (int i = 0; i < 2 * wl2; i++) {
                        int n = i >> 1, par = i & 1;
                        int p = s_par[((ib ^ 1) * 16 + n) * 2 + par];
                        bulk_g2s(raw_sh + (unsigned)((((ib ^ 1) * CHUNK + n) * TWO_D + par * D_) * 4),
                                 g_store + (size_t)p * D_, 512, mg);
                    }
                }

                // wait gather t + weights K-half 0
                if (ib == 0) { mbar_wait(mb_g0, gph0); gph0 ^= 1u; }
                else         { mbar_wait(mb_g1, gph1); gph1 ^= 1u; }
                mbar_wait(mb_w, wph); wph ^= 1u;

                const float* rawb = raw + (size_t)ib * CHUNK * TWO_D;
                float ax0 = bp.x, ay0 = bp.y, ax1 = bp.x, ay1 = bp.y;
                float ax2 = bp.x, ay2 = bp.y, ax3 = bp.x, ay3 = bp.y;

                // ---- K-half 0: k in [0,128) ----
#pragma unroll 4
                for (int k4 = 0; k4 < 32; k4++) {
                    float4 v0 = *(const float4*)(rawb + (g * 4 + 0) * TWO_D + k4 * 4);
                    float4 v1 = *(const float4*)(rawb + (g * 4 + 1) * TWO_D + k4 * 4);
                    float4 v2 = *(const float4*)(rawb + (g * 4 + 2) * TWO_D + k4 * 4);
                    float4 v3 = *(const float4*)(rawb + (g * 4 + 3) * TWO_D + k4 * 4);
#pragma unroll
                    for (int kk = 0; kk < 4; kk++) {
                        float2 w = *(const float2*)(w_s + (k4 * 4 + kk) * D_ + 2 * j);
                        float e0 = kk == 0 ? v0.x : kk == 1 ? v0.y : kk == 2 ? v0.z : v0.w;
                        float e1 = kk == 0 ? v1.x : kk == 1 ? v1.y : kk == 2 ? v1.z : v1.w;
                        float e2 = kk == 0 ? v2.x : kk == 1 ? v2.y : kk == 2 ? v2.z : v2.w;
                        float e3 = kk == 0 ? v3.x : kk == 1 ? v3.y : kk == 2 ? v3.z : v3.w;
                        ax0 = fmaf(w.x, e0, ax0); ay0 = fmaf(w.y, e0, ay0);
                        ax1 = fmaf(w.x, e1, ax1); ay1 = fmaf(w.y, e1, ay1);
                        ax2 = fmaf(w.x, e2, ax2); ay2 = fmaf(w.y, e2, ay2);
                        ax3 = fmaf(w.x, e3, ax3); ay3 = fmaf(w.y, e3, ay3);
                    }
                }
                __syncthreads();            // everyone done reading w_s
                if (tid == 0) {             // weights K-half 1
                    mbar_expect_tx(mb_w, WS_B);
                    bulk_g2s(w_sh, Wr + 128 * D_, WS_B, mb_w);
                }
                mbar_wait(mb_w, wph); wph ^= 1u;

                // ---- K-half 1: k in [128,256) ----
#pragma unroll 4
                for (int k4 = 0; k4 < 32; k4++) {
                    float4 v0 = *(const float4*)(rawb + (g * 4 + 0) * TWO_D + 128 + k4 * 4);
                    float4 v1 = *(const float4*)(rawb + (g * 4 + 1) * TWO_D + 128 + k4 * 4);
                    float4 v2 = *(const float4*)(rawb + (g * 4 + 2) * TWO_D + 128 + k4 * 4);
                    float4 v3 = *(const float4*)(rawb + (g * 4 + 3) * TWO_D + 128 + k4 * 4);
#pragma unroll
                    for (int kk = 0; kk < 4; kk++) {
                        float2 w = *(const float2*)(w_s + (k4 * 4 + kk) * D_ + 2 * j);
                        float e0 = kk == 0 ? v0.x : kk == 1 ? v0.y : kk == 2 ? v0.z : v0.w;
                        float e1 = kk == 0 ? v1.x : kk == 1 ? v1.y : kk == 2 ? v1.z : v1.w;
                        float e2 = kk == 0 ? v2.x : kk == 1 ? v2.y : kk == 2 ? v2.z : v2.w;
                        float e3 = kk == 0 ? v3.x : kk == 1 ? v3.y : kk == 2 ? v3.z : v3.w;
                        ax0 = fmaf(w.x, e0, ax0); ay0 = fmaf(w.y, e0, ay0);
                        ax1 = fmaf(w.x, e1, ax1); ay1 = fmaf(w.y, e1, ay1);
                        ax2 = fmaf(w.x, e2, ax2); ay2 = fmaf(w.y, e2, ay2);
                        ax3 = fmaf(w.x, e3, ax3); ay3 = fmaf(w.y, e3, ay3);
                    }
                }

                // store outputs
                float axs[4] = {ax0, ax1, ax2, ax3};
                float ays[4] = {ay0, ay1, ay2, ay3};
#pragma unroll
                for (int nn = 0; nn < 4; nn++) {
                    int ns = g * 4 + nn;
                    if (ns < wlen) {
                        int m = s_m[ib * 16 + ns];
                        float2 o = make_float2(fmaxf(axs[nn], 0.f), fmaxf(ays[nn], 0.f));
                        *(float2*)(g_store + (size_t)(out0 + m) * D_ + 2 * j) = o;
                    }
                }
                __syncthreads();            // raw[ib], idx[ib], w_s reusable
                if (tid == 0 && t + 1 < nc) {   // weights K-half 0 for next chunk
                    mbar_expect_tx(mb_w, WS_B);
                    bulk_g2s(w_sh, Wr, WS_B, mb_w);
                }
            }
        }

        // ---- software grid barrier between levels ----
        __threadfence();
        __syncthreads();
        if (lvl < LVLS - 1) {
            if (tid == 0) {
                atomicAdd(&g_bar, 1u);
                unsigned target = (unsigned)(lvl + 1) * PBLK;
                while (*(volatile unsigned*)&g_bar < target) __nanosleep(128);
            }
            __syncthreads();
            __threadfence();
        } else {
            if (tid == 0) {
                unsigned old = atomicAdd(&g_bar, 1u);
                if (old == (unsigned)LVLS * PBLK - 1u)
                    atomicExch(&g_bar, 0u);   // reset for next graph replay
            }
        }
    }
}

// ---------------- 4. eval: MLP=4 batched, deterministic reduce ---------------
__global__ void k_eval(const float* __restrict__ eval_w,
                       const float* __restrict__ eval_b,
                       const float* __restrict__ pos_vals,
                       const float* __restrict__ neg_vals) {
    int warp = threadIdx.x >> 5, lane = threadIdx.x & 31;
    int nwarps = gridDim.x * (blockDim.x >> 5);
    int gw = blockIdx.x * (blockDim.x >> 5) + warp;

    const float4 wv = *(const float4*)(eval_w + lane * 4);
    float eb = eval_b[0];

    double s1 = 0, s2 = 0, pok = 0, nok = 0, sp = 0, sn = 0;

    for (int base = gw * 4; base < NTOT; base += nwarps * 4) {
        float d[4];
#pragma unroll
        for (int i = 0; i < 4; i++) {
            float4 x = make_float4(0.f, 0.f, 0.f, 0.f);
            if (base + i < NTOT)
                x = *(const float4*)(g_store + (size_t)(base + i) * D_ + lane * 4);
            d[i] = x.x * wv.x + x.y * wv.y + x.z * wv.z + x.w * wv.w;
        }
#pragma unroll
        for (int o = 16; o > 0; o >>= 1) {
#pragma unroll
            for (int i = 0; i < 4; i++)
                d[i] += __shfl_xor_sync(0xFFFFFFFFu, d[i], o);
        }
        if (lane == 0) {
#pragma unroll
            for (int i = 0; i < 4; i++) {
                int node = base + i;
                if (node < NTOT) {
                    float logit = d[i] + eb;
                    float p = pos_vals[node], n = neg_vals[node];
                    s1 += (double)(p * softplusf(-logit));
                    s2 += (double)(n * softplusf(logit));
                    if (logit >= 0.0f) pok += (double)p; else nok += (double)n;
                    sp += (double)p; sn += (double)n;
                }
            }
        }
    }

    __shared__ double sd[8][6];
    if (lane == 0) {
        sd[warp][0] = s1; sd[warp][1] = s2; sd[warp][2] = pok;
        sd[warp][3] = nok; sd[warp][4] = sp; sd[warp][5] = sn;
    }
    __syncthreads();
    if (threadIdx.x == 0) {
        double v[6] = {0, 0, 0, 0, 0, 0};
        for (int w = 0; w < 8; w++)
            for (int c2 = 0; c2 < 6; c2++) v[c2] += sd[w][c2];
        for (int c2 = 0; c2 < 6; c2++) g_part[blockIdx.x * 8 + c2] = v[c2];
    }
}

__global__ void k_final(float* __restrict__ out) {
    __shared__ double sh[6][256];
    int tid = threadIdx.x;
    double v[6] = {0, 0, 0, 0, 0, 0};
    for (int b = tid; b < EVAL_BLOCKS; b += 256)
        for (int c2 = 0; c2 < 6; c2++) v[c2] += g_part[b * 8 + c2];
    for (int c2 = 0; c2 < 6; c2++) sh[c2][tid] = v[c2];
    __syncthreads();
    for (int s = 128; s > 0; s >>= 1) {
        if (tid < s)
            for (int c2 = 0; c2 < 6; c2++) sh[c2][tid] += sh[c2][tid + s];
        __syncthreads();
    }
    if (tid == 0) {
        double S1 = sh[0][0], S2 = sh[1][0], pok = sh[2][0];
        double nok = sh[3][0], sp = sh[4][0], sn = sh[5][0];
        double pw = sn / sp;
        out[0] = (float)(pw * S1 + S2);
        out[1] = (float)pok;
        out[2] = (float)nok;
    }
}

// ---------------- launch ----------------
extern "C" void kernel_launch(void* const* d_in, const int* in_sizes, int n_in,
                              void* d_out, int out_size) {
    const float* thax_table = (const float*)d_in[0];
    const float* sine_table = (const float*)d_in[1];
    const float* rule_W     = (const float*)d_in[2];
    const float* rule_b     = (const float*)d_in[3];
    const float* eval_w     = (const float*)d_in[4];
    const float* eval_b     = (const float*)d_in[5];
    const float* pos_vals   = (const float*)d_in[6];
    const float* neg_vals   = (const float*)d_in[7];
    const int*   init_thax  = (const int*)d_in[8];
    const int*   init_sine  = (const int*)d_in[9];
    const int*   parents    = (const int*)d_in[10];
    const int*   rules      = (const int*)d_in[11];

    (void)in_sizes; (void)n_in; (void)out_size;

    cudaFuncSetAttribute(k_levels, cudaFuncAttributeMaxDynamicSharedMemorySize,
                         SMEM_LVL);

    k_init<<<(NINIT * 32 + 255) / 256, 256>>>(thax_table, sine_table, init_thax, init_sine);
    k_group<<<LVLS, 256>>>(rules);
    k_levels<<<PBLK, 256, SMEM_LVL>>>(rule_W, rule_b, parents);
    k_eval<<<EVAL_BLOCKS, 256>>>(eval_w, eval_b, pos_vals, neg_vals);
    k_final<<<1, 256>>>((float*)d_out);
}

// round 17
// speedup vs baseline: 1.4700x; 1.0367x over previous
#include <cuda_runtime.h>

// ---------------- problem constants ----------------
#define D_      128
#define TWO_D   256
#define NINIT   100000
#define LVLS    64
#define MM      4096
#define NRULES  256
#define NTOT    (NINIT + LVLS * MM)   // 362144

#define EVAL_BLOCKS 1024
#define CHUNK 16     // nodes per gather chunk (4 g-slots x NN=4)

// dynamic smem for k_levels:
//   w_s  float[2][64][128]  65536 B  (double-buffered 32KB weight quarters)
//   raw  float[2][16][256]  32768 B  (gathered parents, dbl buf)
//   s_m  int[2][16], s_par int[2][16][2], mbar u64[4]
#define QW_B  32768
#define RAW_B 32768
#define SMEM_LVL (2 * QW_B + RAW_B + 512 + 64)   // ~96.8 KB -> 2 blocks/SM

// ---------------- device scratch (static: no allocs allowed) ----------------
__device__ float    g_store[(size_t)NTOT * D_];     // ~185 MB embedding store
__device__ int      g_order[LVLS * MM];
__device__ int      g_off[LVLS * (NRULES + 1)];
__device__ double   g_part[EVAL_BLOCKS * 8];
__device__ unsigned g_bar;                          // grid barrier (0 at rest)

// ---------------- helpers ----------------
__device__ __forceinline__ void mbar_init(unsigned mbar, unsigned count) {
    asm volatile("mbarrier.init.shared.b64 [%0], %1;" :: "r"(mbar), "r"(count) : "memory");
}
__device__ __forceinline__ void mbar_expect_tx(unsigned mbar, unsigned bytes) {
    asm volatile("mbarrier.arrive.expect_tx.shared.b64 _, [%0], %1;"
                 :: "r"(mbar), "r"(bytes) : "memory");
}
__device__ __forceinline__ void bulk_g2s(unsigned dst, const void* src,
                                         unsigned bytes, unsigned mbar) {
    asm volatile("cp.async.bulk.shared::cta.global.mbarrier::complete_tx::bytes "
                 "[%0], [%1], %2, [%3];"
                 :: "r"(dst), "l"(src), "r"(bytes), "r"(mbar) : "memory");
}
__device__ __forceinline__ void mbar_wait(unsigned mbar, unsigned phase) {
    asm volatile(
        "{\n\t"
        ".reg .pred p;\n\t"
        "WL%=:\n\t"
        "mbarrier.try_wait.parity.acquire.cta.shared::cta.b64 p, [%0], %1, 0x989680;\n\t"
        "@!p bra WL%=;\n\t"
        "}"
        :: "r"(mbar), "r"(phase) : "memory");
}
__device__ __forceinline__ float softplusf(float x) {
    return fmaxf(x, 0.0f) + log1pf(expf(-fabsf(x)));
}

// ---------------- 1. init embeddings ----------------
__global__ void k_init(const float* __restrict__ thax_table,
                       const float* __restrict__ sine_table,
                       const int* __restrict__ init_thax,
                       const int* __restrict__ init_sine) {
    int idx = blockIdx.x * blockDim.x + threadIdx.x;
    if (idx >= NINIT * 32) return;
    int row = idx >> 5, q = idx & 31;
    int t = init_thax[row], s = init_sine[row];
    const float4 a = *(const float4*)(thax_table + (size_t)t * D_ + q * 4);
    const float4 b = *(const float4*)(sine_table + (size_t)s * D_ + q * 4);
    float4 o; o.x = a.x + b.x; o.y = a.y + b.y; o.z = a.z + b.z; o.w = a.w + b.w;
    *(float4*)(g_store + (size_t)row * D_ + q * 4) = o;
}

// ---------------- 2. bucket nodes by rule, per level ----------------
__global__ void k_group(const int* __restrict__ rules) {
    int l = blockIdx.x;
    int tid = threadIdx.x;                    // 256 threads
    __shared__ int cnt[NRULES];
    __shared__ int base[NRULES];
    cnt[tid] = 0;
    __syncthreads();
    for (int m = tid; m < MM; m += 256)
        atomicAdd(&cnt[rules[l * MM + m]], 1);
    __syncthreads();
    if (tid == 0) {
        int acc = 0;
        for (int r = 0; r < NRULES; r++) { base[r] = acc; acc += cnt[r]; }
    }
    __syncthreads();
    g_off[l * (NRULES + 1) + tid] = base[tid];
    if (tid == 0) g_off[l * (NRULES + 1) + NRULES] = MM;
    cnt[tid] = 0;
    __syncthreads();
    for (int m = tid; m < MM; m += 256) {
        int r = rules[l * MM + m];
        int pos = base[r] + atomicAdd(&cnt[r], 1);
        g_order[l * MM + pos] = m;
    }
}

// ---------------- 3. persistent level kernel -------------------------------
// grid computed from occupancy (target 256 blocks, 2/SM). Blocks stride over
// rules; each rule's full 128 output cols handled by one block per chunk of
// 16 nodes (NN=4). Weights stream as four 32KB quarters through a 2-buffer
// pipeline (issue q+2 after computing q) so weight waits are pre-completed;
// gathers are bulk-DMA double-buffered one chunk ahead. Levels separated by
// a software grid barrier keyed to gridDim.x.
__global__ void __launch_bounds__(256, 2) k_levels(
    const float* __restrict__ rule_W, const float* __restrict__ rule_b,
    const int* __restrict__ parents) {

    extern __shared__ __align__(16) char sm[];
    float* w_s = (float*)sm;                           // [2][64][128]
    float* raw = (float*)(sm + 2 * QW_B);              // [2][16][256]
    int*   s_m   = (int*)(sm + 2 * QW_B + RAW_B);      // [2][16]
    int*   s_par = s_m + 32;                           // [2][16][2]
    unsigned long long* mb = (unsigned long long*)(s_par + 64);  // w0,w1,g0,g1

    unsigned mb_w0 = (unsigned)__cvta_generic_to_shared(&mb[0]);
    unsigned mb_w1 = (unsigned)__cvta_generic_to_shared(&mb[1]);
    unsigned mb_g0 = (unsigned)__cvta_generic_to_shared(&mb[2]);
    unsigned mb_g1 = (unsigned)__cvta_generic_to_shared(&mb[3]);
    unsigned w_sh   = (unsigned)__cvta_generic_to_shared(w_s);
    unsigned raw_sh = (unsigned)__cvta_generic_to_shared(raw);

    int tid = threadIdx.x;
    int j   = tid & 63;            // col-pair 0..63 (cols 2j, 2j+1)
    int jj  = 2 * j;
    int g4  = (tid >> 6) * 4;      // node base within chunk (0,4,8,12)

    if (tid == 0) {
        mbar_init(mb_w0, 1); mbar_init(mb_w1, 1);
        mbar_init(mb_g0, 1); mbar_init(mb_g1, 1);
    }
    __syncthreads();

    unsigned wph0 = 0, wph1 = 0, gph0 = 0, gph1 = 0;

    for (int lvl = 0; lvl < LVLS; lvl++) {
        int out0 = NINIT + lvl * MM;

        for (int r = blockIdx.x; r < NRULES; r += gridDim.x) {
            int off0 = g_off[lvl * (NRULES + 1) + r];
            int c = g_off[lvl * (NRULES + 1) + r + 1] - off0;
            if (c == 0) continue;

            const float* Wr = rule_W + (size_t)r * TWO_D * D_;
            float2 bp = *(const float2*)(rule_b + (size_t)r * D_ + jj);
            int nc = (c + CHUNK - 1) / CHUNK;

            // stage idx for chunk 0 (parity 0)
            {
                int wl = min(CHUNK, c);
                if (tid < 2 * wl) {
                    int n = tid >> 1, pw = tid & 1;
                    int m = g_order[lvl * MM + off0 + n];
                    int p = parents[((size_t)lvl * MM + m) * 2 + pw];
                    if (pw == 0) s_m[n] = m;
                    s_par[n * 2 + pw] = p;
                }
            }
            __syncthreads();
            if (tid == 0) {                       // gather chunk 0 -> raw[0]
                int wl = min(CHUNK, c);
                mbar_expect_tx(mb_g0, (unsigned)(wl * 2 * 512));
                for (int i = 0; i < 2 * wl; i++) {
                    int n = i >> 1, par = i & 1;
                    int p = s_par[n * 2 + par];
                    bulk_g2s(raw_sh + (unsigned)((n * TWO_D + par * D_) * 4),
                             g_store + (size_t)p * D_, 512, mb_g0);
                }
            }

            for (int t = 0; t < nc; t++) {
                int ib = t & 1;
                int wlen = min(CHUNK, c - t * CHUNK);

                if (tid == 0) {                   // weight quarters 0 and 1
                    mbar_expect_tx(mb_w0, QW_B);
                    bulk_g2s(w_sh, Wr, QW_B, mb_w0);
                    mbar_expect_tx(mb_w1, QW_B);
                    bulk_g2s(w_sh + QW_B, Wr + 64 * D_, QW_B, mb_w1);
                }

                // wait gather for this chunk
                if (ib == 0) { mbar_wait(mb_g0, gph0); gph0 ^= 1u; }
                else         { mbar_wait(mb_g1, gph1); gph1 ^= 1u; }

                const float* rawb = raw + (size_t)ib * CHUNK * TWO_D;
                float ax0 = bp.x, ay0 = bp.y, ax1 = bp.x, ay1 = bp.y;
                float ax2 = bp.x, ay2 = bp.y, ax3 = bp.x, ay3 = bp.y;

#pragma unroll 1
                for (int q = 0; q < 4; q++) {
                    int wb = q & 1;
                    if (wb == 0) { mbar_wait(mb_w0, wph0); wph0 ^= 1u; }
                    else         { mbar_wait(mb_w1, wph1); wph1 ^= 1u; }

                    const float* wq = w_s + wb * (QW_B / 4);   // [64][128]
                    const float* rq = rawb + q * 64;

#pragma unroll 4
                    for (int k4 = 0; k4 < 16; k4++) {
                        float4 v0 = *(const float4*)(rq + (g4 + 0) * TWO_D + k4 * 4);
                        float4 v1 = *(const float4*)(rq + (g4 + 1) * TWO_D + k4 * 4);
                        float4 v2 = *(const float4*)(rq + (g4 + 2) * TWO_D + k4 * 4);
                        float4 v3 = *(const float4*)(rq + (g4 + 3) * TWO_D + k4 * 4);
                        float2 wA = *(const float2*)(wq + (k4 * 4 + 0) * D_ + jj);
                        float2 wB = *(const float2*)(wq + (k4 * 4 + 1) * D_ + jj);
                        float2 wC = *(const float2*)(wq + (k4 * 4 + 2) * D_ + jj);
                        float2 wD = *(const float2*)(wq + (k4 * 4 + 3) * D_ + jj);
#define STEP_(w_, e0, e1, e2, e3) \
    ax0 = fmaf(w_.x, e0, ax0); ay0 = fmaf(w_.y, e0, ay0); \
    ax1 = fmaf(w_.x, e1, ax1); ay1 = fmaf(w_.y, e1, ay1); \
    ax2 = fmaf(w_.x, e2, ax2); ay2 = fmaf(w_.y, e2, ay2); \
    ax3 = fmaf(w_.x, e3, ax3); ay3 = fmaf(w_.y, e3, ay3);
                        STEP_(wA, v0.x, v1.x, v2.x, v3.x)
                        STEP_(wB, v0.y, v1.y, v2.y, v3.y)
                        STEP_(wC, v0.z, v1.z, v2.z, v3.z)
                        STEP_(wD, v0.w, v1.w, v2.w, v3.w)
#undef STEP_
                    }
                    __syncthreads();               // all warps done with wq[wb]

                    if (q < 2 && tid == 0) {       // prefetch quarter q+2
                        unsigned mw = wb ? mb_w1 : mb_w0;
                        mbar_expect_tx(mw, QW_B);
                        bulk_g2s(w_sh + wb * QW_B, Wr + (q + 2) * 64 * D_, QW_B, mw);
                    }
                    if (q == 0 && t + 1 < nc) {    // stage idx chunk t+1
                        int wl2 = min(CHUNK, c - (t + 1) * CHUNK);
                        if (tid < 2 * wl2) {
                            int n = tid >> 1, pw = tid & 1;
                            int m = g_order[lvl * MM + off0 + (t + 1) * CHUNK + n];
                            int p = parents[((size_t)lvl * MM + m) * 2 + pw];
                            if (pw == 0) s_m[(ib ^ 1) * 16 + n] = m;
                            s_par[((ib ^ 1) * 16 + n) * 2 + pw] = p;
                        }
                    }
                    if (q == 1 && t + 1 < nc && tid == 0) {   // gather chunk t+1
                        int wl2 = min(CHUNK, c - (t + 1) * CHUNK);
                        unsigned mg = (ib ^ 1) ? mb_g1 : mb_g0;
                        mbar_expect_tx(mg, (unsigned)(wl2 * 2 * 512));
                        for (int i = 0; i < 2 * wl2; i++) {
                            int n = i >> 1, par = i & 1;
                            int p = s_par[((ib ^ 1) * 16 + n) * 2 + par];
                            bulk_g2s(raw_sh + (unsigned)((((ib ^ 1) * CHUNK + n) * TWO_D + par * D_) * 4),
                                     g_store + (size_t)p * D_, 512, mg);
                        }
                    }
                }

                // ReLU + store (guarded)
                float axs[4] = {ax0, ax1, ax2, ax3};
                float ays[4] = {ay0, ay1, ay2, ay3};
#pragma unroll
                for (int nn = 0; nn < 4; nn++) {
                    int ns = g4 + nn;
                    if (ns < wlen) {
                        int m = s_m[ib * 16 + ns];
                        float2 o = make_float2(fmaxf(axs[nn], 0.f), fmaxf(ays[nn], 0.f));
                        *(float2*)(g_store + (size_t)(out0 + m) * D_ + jj) = o;
                    }
                }
            }
        }

        // ---- software grid barrier between levels ----
        __threadfence();
        __syncthreads();
        if (lvl < LVLS - 1) {
            if (tid == 0) {
                atomicAdd(&g_bar, 1u);
                unsigned target = (unsigned)(lvl + 1) * gridDim.x;
                while (*(volatile unsigned*)&g_bar < target) __nanosleep(128);
            }
            __syncthreads();
            __threadfence();
        } else {
            if (tid == 0) {
                unsigned old = atomicAdd(&g_bar, 1u);
                if (old == (unsigned)LVLS * gridDim.x - 1u)
                    atomicExch(&g_bar, 0u);   // reset for next graph replay
            }
        }
    }
}

// ---------------- 4. eval: MLP=8, lane-distributed tail ----------------------
__global__ void k_eval(const float* __restrict__ eval_w,
                       const float* __restrict__ eval_b,
                       const float* __restrict__ pos_vals,
                       const float* __restrict__ neg_vals) {
    int warp = threadIdx.x >> 5, lane = threadIdx.x & 31;
    int nwarps = gridDim.x * (blockDim.x >> 5);
    int gw = blockIdx.x * (blockDim.x >> 5) + warp;

    const float4 wv = *(const float4*)(eval_w + lane * 4);
    float eb = eval_b[0];

    double s1 = 0, s2 = 0, pok = 0, nok = 0, sp = 0, sn = 0;

    for (int base = gw * 8; base < NTOT; base += nwarps * 8) {
        float d[8];
#pragma unroll
        for (int i = 0; i < 8; i++) {
            float4 x = make_float4(0.f, 0.f, 0.f, 0.f);
            if (base + i < NTOT)
                x = *(const float4*)(g_store + (size_t)(base + i) * D_ + lane * 4);
            d[i] = x.x * wv.x + x.y * wv.y + x.z * wv.z + x.w * wv.w;
        }
#pragma unroll
        for (int o = 16; o > 0; o >>= 1) {
#pragma unroll
            for (int i = 0; i < 8; i++)
                d[i] += __shfl_xor_sync(0xFFFFFFFFu, d[i], o);
        }
        if (lane < 8 && base + lane < NTOT) {
            int node = base + lane;
            float logit = d[lane] + eb;
            float p = pos_vals[node], n = neg_vals[node];
            s1 += (double)(p * softplusf(-logit));
            s2 += (double)(n * softplusf(logit));
            if (logit >= 0.0f) pok += (double)p; else nok += (double)n;
            sp += (double)p; sn += (double)n;
        }
    }

    // combine lanes 0..7 (others hold zeros)
#pragma unroll
    for (int o = 4; o > 0; o >>= 1) {
        s1  += __shfl_xor_sync(0xFFFFFFFFu, s1, o);
        s2  += __shfl_xor_sync(0xFFFFFFFFu, s2, o);
        pok += __shfl_xor_sync(0xFFFFFFFFu, pok, o);
        nok += __shfl_xor_sync(0xFFFFFFFFu, nok, o);
        sp  += __shfl_xor_sync(0xFFFFFFFFu, sp, o);
        sn  += __shfl_xor_sync(0xFFFFFFFFu, sn, o);
    }

    __shared__ double sd[8][6];
    if (lane == 0) {
        sd[warp][0] = s1; sd[warp][1] = s2; sd[warp][2] = pok;
        sd[warp][3] = nok; sd[warp][4] = sp; sd[warp][5] = sn;
    }
    __syncthreads();
    if (threadIdx.x == 0) {
        double v[6] = {0, 0, 0, 0, 0, 0};
        for (int w = 0; w < 8; w++)
            for (int c2 = 0; c2 < 6; c2++) v[c2] += sd[w][c2];
        for (int c2 = 0; c2 < 6; c2++) g_part[blockIdx.x * 8 + c2] = v[c2];
    }
}

__global__ void k_final(float* __restrict__ out) {
    __shared__ double sh[6][256];
    int tid = threadIdx.x;
    double v[6] = {0, 0, 0, 0, 0, 0};
    for (int b = tid; b < EVAL_BLOCKS; b += 256)
        for (int c2 = 0; c2 < 6; c2++) v[c2] += g_part[b * 8 + c2];
    for (int c2 = 0; c2 < 6; c2++) sh[c2][tid] = v[c2];
    __syncthreads();
    for (int s = 128; s > 0; s >>= 1) {
        if (tid < s)
            for (int c2 = 0; c2 < 6; c2++) sh[c2][tid] += sh[c2][tid + s];
        __syncthreads();
    }
    if (tid == 0) {
        double S1 = sh[0][0], S2 = sh[1][0], pok = sh[2][0];
        double nok = sh[3][0], sp = sh[4][0], sn = sh[5][0];
        double pw = sn / sp;
        out[0] = (float)(pw * S1 + S2);
        out[1] = (float)pok;
        out[2] = (float)nok;
    }
}

// ---------------- launch ----------------
extern "C" void kernel_launch(void* const* d_in, const int* in_sizes, int n_in,
                              void* d_out, int out_size) {
    const float* thax_table = (const float*)d_in[0];
    const float* sine_table = (const float*)d_in[1];
    const float* rule_W     = (const float*)d_in[2];
    const float* rule_b     = (const float*)d_in[3];
    const float* eval_w     = (const float*)d_in[4];
    const float* eval_b     = (const float*)d_in[5];
    const float* pos_vals   = (const float*)d_in[6];
    const float* neg_vals   = (const float*)d_in[7];
    const int*   init_thax  = (const int*)d_in[8];
    const int*   init_sine  = (const int*)d_in[9];
    const int*   parents    = (const int*)d_in[10];
    const int*   rules      = (const int*)d_in[11];

    (void)in_sizes; (void)n_in; (void)out_size;

    cudaFuncSetAttribute(k_levels, cudaFuncAttributeMaxDynamicSharedMemorySize,
                         SMEM_LVL);

    // deterministic, allocation-free: size the persistent grid so ALL blocks
    // are resident (grid barrier requires it)
    int sms = 0, perSm = 0;
    cudaDeviceGetAttribute(&sms, cudaDevAttrMultiProcessorCount, 0);
    cudaOccupancyMaxActiveBlocksPerMultiprocessor(&perSm, k_levels, 256, SMEM_LVL);
    if (perSm < 1) perSm = 1;
    int grid = perSm * sms;
    if (grid > NRULES) grid = NRULES;

    k_init<<<(NINIT * 32 + 255) / 256, 256>>>(thax_table, sine_table, init_thax, init_sine);
    k_group<<<LVLS, 256>>>(rules);
    k_levels<<<grid, 256, SMEM_LVL>>>(rule_W, rule_b, parents);
    k_eval<<<EVAL_BLOCKS, 256>>>(eval_w, eval_b, pos_vals, neg_vals);
    k_final<<<1, 256>>>((float*)d_out);
}